// round 10
// baseline (speedup 1.0000x reference)
#include <cuda_runtime.h>

#define BB 2
#define NN 8192
#define II 32
#define EE 128
#define HH 64
#define NW (NN/32)

// ---------------- device scratch ----------------
__device__ float d_W1r[HH*3];
__device__ float d_A1r[4*3];
__device__ float d_B1r[HH*4];
__device__ float d_W2r[EE*HH];     // [e][c]
__device__ float d_A2r[4*HH];      // [r][c]
__device__ float d_B2r[EE*4];      // [e][r]
__device__ float d_Wpr[EE*3];      // [e][j]
__device__ float d_Wd1t[EE*HH];    // TRANSPOSED [e][k]
__device__ float d_Wd2r[HH];
__device__ float d_pe[BB*II*EE];
__device__ float d_ped[BB*II*EE];  // pe - neg_embed
__device__ unsigned d_mask[BB*II*NW];

// TF32 round-to-nearest-even (matches cublas input rounding)
__device__ __forceinline__ float tf32r(float x) {
    float y;
    asm("cvt.rna.tf32.f32 %0, %1;" : "=f"(y) : "f"(x));
    return y;
}

// ---------------- threefry2x32, key=(0,42) ----------------
__device__ __forceinline__ void threefry_0_42(unsigned x0, unsigned x1,
                                              unsigned& o0, unsigned& o1) {
    const unsigned k0 = 0u, k1 = 42u;
    const unsigned k2 = 0x1BD11BDAu ^ k0 ^ k1;
    unsigned v0 = x0 + k0, v1 = x1 + k1;
#define TF_R(r) { v0 += v1; v1 = (v1 << (r)) | (v1 >> (32 - (r))); v1 ^= v0; }
    TF_R(13) TF_R(15) TF_R(26) TF_R(6)   v0 += k1; v1 += k2 + 1u;
    TF_R(17) TF_R(29) TF_R(16) TF_R(24)  v0 += k2; v1 += k0 + 2u;
    TF_R(13) TF_R(15) TF_R(26) TF_R(6)   v0 += k0; v1 += k1 + 3u;
    TF_R(17) TF_R(29) TF_R(16) TF_R(24)  v0 += k1; v1 += k2 + 4u;
    TF_R(13) TF_R(15) TF_R(26) TF_R(6)   v0 += k2; v1 += k0 + 5u;
#undef TF_R
    o0 = v0; o1 = v1;
}

// ---------------- K0: round weights + pos_embed ----------------
__global__ void k_setup(const float* __restrict__ W1, const float* __restrict__ A1,
                        const float* __restrict__ B1, const float* __restrict__ W2,
                        const float* __restrict__ A2, const float* __restrict__ B2,
                        const float* __restrict__ Wp, const float* __restrict__ bp,
                        const float* __restrict__ Wd1, const float* __restrict__ Wd2,
                        const float* __restrict__ pos_coords) {
    int t = threadIdx.x;
    for (int i = t; i < HH*3;  i += 1024) d_W1r[i] = tf32r(W1[i]);
    for (int i = t; i < 12;    i += 1024) d_A1r[i] = tf32r(A1[i]);
    for (int i = t; i < HH*4;  i += 1024) d_B1r[i] = tf32r(B1[i]);
    for (int i = t; i < EE*HH; i += 1024) d_W2r[i] = tf32r(W2[i]);
    for (int i = t; i < 4*HH;  i += 1024) d_A2r[i] = tf32r(A2[i]);
    for (int i = t; i < EE*4;  i += 1024) d_B2r[i] = tf32r(B2[i]);
    for (int i = t; i < EE*3;  i += 1024) d_Wpr[i] = tf32r(Wp[i]);
    for (int i = t; i < HH;    i += 1024) d_Wd2r[i] = tf32r(Wd2[i]);
    for (int i = t; i < EE*HH; i += 1024) {
        int e = i >> 6, k = i & 63;
        d_Wd1t[i] = tf32r(Wd1[k*EE + e]);
    }
    __syncthreads();
    // pos_embed = tf32(pos) @ Wpr.T + bp
    for (int i = t; i < BB*II*EE; i += 1024) {
        int bi = i >> 7, e = i & 127;
        float p0 = tf32r(pos_coords[bi*3+0]);
        float p1 = tf32r(pos_coords[bi*3+1]);
        float p2 = tf32r(pos_coords[bi*3+2]);
        d_pe[i] = p0*d_Wpr[e*3] + p1*d_Wpr[e*3+1] + p2*d_Wpr[e*3+2] + bp[e];
    }
}

// ---------------- K1: encoder (TF32-emulated LoRA chain) ----------------
__global__ __launch_bounds__(128) void k_encoder(const float* __restrict__ points,
                                                 float* __restrict__ out_pf) {
    __shared__ float sW2r[EE*HH];
    __shared__ float sB2r[EE*4];
    __shared__ float sW1r[HH*3];
    __shared__ float sA1r[12];
    __shared__ float sB1r[HH*4];
    __shared__ float sA2r[4*HH];
    int t = threadIdx.x;
    for (int i = t; i < EE*HH; i += 128) sW2r[i] = d_W2r[i];
    for (int i = t; i < EE*4;  i += 128) sB2r[i] = d_B2r[i];
    for (int i = t; i < HH*3;  i += 128) sW1r[i] = d_W1r[i];
    for (int i = t; i < 12;    i += 128) sA1r[i] = d_A1r[i];
    for (int i = t; i < HH*4;  i += 128) sB1r[i] = d_B1r[i];
    for (int i = t; i < 4*HH;  i += 128) sA2r[i] = d_A2r[i];
    __syncthreads();

    int m = blockIdx.x * 128 + t;   // 0..16383
    float p0 = tf32r(points[m*3]), p1 = tf32r(points[m*3+1]), p2 = tf32r(points[m*3+2]);

    // rank-4 lora1: u = x@A1.T (tf32), rounded
    float ur[4];
    #pragma unroll
    for (int r = 0; r < 4; r++)
        ur[r] = tf32r(p0*sA1r[r*3] + p1*sA1r[r*3+1] + p2*sA1r[r*3+2]);

    float h1r[HH];
    #pragma unroll 4
    for (int c = 0; c < HH; c++) {
        float t1 = p0*sW1r[c*3] + p1*sW1r[c*3+1] + p2*sW1r[c*3+2];
        float l1 = ur[0]*sB1r[c*4] + ur[1]*sB1r[c*4+1] + ur[2]*sB1r[c*4+2] + ur[3]*sB1r[c*4+3];
        float h = t1 + 0.25f*l1;
        h1r[c] = tf32r(fmaxf(h, 0.f));
    }

    // rank-4 lora2 branch
    float vr[4];
    #pragma unroll
    for (int r = 0; r < 4; r++) {
        float s = 0.f;
        #pragma unroll 8
        for (int c = 0; c < HH; c++) s += h1r[c]*sA2r[r*HH + c];
        vr[r] = tf32r(s);
    }

    float4* pout = (float4*)(out_pf + (size_t)m * EE);
    #pragma unroll 2
    for (int e4 = 0; e4 < 32; e4++) {
        float o[4];
        #pragma unroll
        for (int q = 0; q < 4; q++) {
            int e = e4*4 + q;
            float s = 0.f;
            #pragma unroll 8
            for (int c = 0; c < HH; c++) s += h1r[c]*sW2r[e*HH + c];
            float l2 = vr[0]*sB2r[e*4] + vr[1]*sB2r[e*4+1] + vr[2]*sB2r[e*4+2] + vr[3]*sB2r[e*4+3];
            o[q] = s + 0.25f*l2;
        }
        pout[e4] = make_float4(o[0], o[1], o[2], o[3]);
    }
}

// ---------------- K2/K4: TF32-emulated decode ----------------
// grid (ntile=64, i=32, b=2), 128 threads. mode 0: masks; mode 1: refined logits.
#define XS_STR 136
#define WD_STR 66
__global__ __launch_bounds__(128) void k_decode(const float* __restrict__ pf,
                                                const float* __restrict__ pesrc,
                                                const float* __restrict__ bd1,
                                                const float* __restrict__ bd2,
                                                int mode, float* __restrict__ out) {
    extern __shared__ float sm[];
    float* xs   = sm;                    // [128][XS_STR]
    float* swd1 = sm + 128*XS_STR;       // [e][WD_STR] -> [e][k]
    float* hid  = swd1 + EE*WD_STR;      // [n][WD_STR]
    float* spe  = hid + 128*WD_STR;      // [128]
    float* sbd1 = spe + 128;             // [64]
    float* swd2 = sbd1 + 64;             // [64]

    int t = threadIdx.x;
    int ntile = blockIdx.x, i = blockIdx.y, b = blockIdx.z;
    int base = ntile * 128;

    // phase A: stage weights, pe row, build rounded xs
    for (int it = 0; it < 64; it++) {
        int idx = t + 128*it;
        int e = idx >> 6, k = idx & 63;
        swd1[e*WD_STR + k] = d_Wd1t[idx];
    }
    if (t < 128) spe[t] = pesrc[(b*II + i)*EE + t];
    if (t < 64)  { sbd1[t] = bd1[t]; swd2[t] = d_Wd2r[t]; }
    __syncthreads();

    const float4* pfb = (const float4*)(pf + ((size_t)(b*NN + base)) * EE);
    #pragma unroll 4
    for (int it = 0; it < 32; it++) {
        int idx4 = t + 128*it;           // 0..4095
        int n = idx4 >> 5, e4 = idx4 & 31;
        float4 pv = __ldg(&pfb[(size_t)n*32 + e4]);
        float4 qv = *(const float4*)&spe[e4*4];
        float4 xv;
        xv.x = tf32r(pv.x + qv.x); xv.y = tf32r(pv.y + qv.y);
        xv.z = tf32r(pv.z + qv.z); xv.w = tf32r(pv.w + qv.w);
        *(float4*)&xs[n*XS_STR + e4*4] = xv;
    }
    __syncthreads();

    // phase B: hidden[n][k] = xs . wd1, 8n x 8k per thread (k = kg + 8*kk)
    int kg = t & 7, ng = t >> 3;
    int n0 = ng * 8;
    float acc[8][8];
    #pragma unroll
    for (int a = 0; a < 8; a++)
        #pragma unroll
        for (int c = 0; c < 8; c++) acc[a][c] = 0.f;

    #pragma unroll 2
    for (int e = 0; e < EE; e++) {
        float w[8], x[8];
        #pragma unroll
        for (int kk = 0; kk < 8; kk++) w[kk] = swd1[e*WD_STR + kg + 8*kk];
        #pragma unroll
        for (int nn = 0; nn < 8; nn++) x[nn] = xs[(n0+nn)*XS_STR + e];
        #pragma unroll
        for (int nn = 0; nn < 8; nn++)
            #pragma unroll
            for (int kk = 0; kk < 8; kk++)
                acc[nn][kk] += x[nn] * w[kk];
    }
    #pragma unroll
    for (int nn = 0; nn < 8; nn++)
        #pragma unroll
        for (int kk = 0; kk < 8; kk++) {
            int k = kg + 8*kk;
            float h = acc[nn][kk] + sbd1[k];
            hid[(n0+nn)*WD_STR + k] = tf32r(fmaxf(h, 0.f));
        }
    __syncthreads();

    // phase C: logit per n
    int n = t;
    float lg = bd2[0];
    #pragma unroll 8
    for (int k = 0; k < HH; k++) lg += hid[n*WD_STR + k] * swd2[k];

    if (mode == 0) {
        unsigned ball = __ballot_sync(0xffffffffu, lg > 0.f);
        if ((t & 31) == 0)
            d_mask[(b*II + i)*NW + (base >> 5) + (t >> 5)] = ball;
    } else {
        out[((size_t)(b*II + i))*NN + base + n] = lg;
    }
}

// ---------------- K3: IoU + gumbel-max pick + (pe - neg_embed) ----------------
__global__ __launch_bounds__(1024) void k_sample(const float* __restrict__ pos_coords,
                                                 const float* __restrict__ bp) {
    __shared__ int   s_inter[II * II];
    __shared__ float s_negc[II * 3];
    int b = blockIdx.x;
    int t = threadIdx.x;
    int i = t >> 5, j = t & 31;

    const unsigned* mi = d_mask + (b*II + i) * NW;
    const unsigned* mj = d_mask + (b*II + j) * NW;
    int cnt = 0;
    #pragma unroll 4
    for (int w = 0; w < NW; w++) cnt += __popc(mi[w] & mj[w]);
    s_inter[i*II + j] = cnt;
    __syncthreads();

    bool cand = false;
    if (i != j) {
        float inter = (float)s_inter[i*II + j];
        float uni = (float)(s_inter[i*II + i] + s_inter[j*II + j]) - inter;
        cand = (inter / (uni + 1e-6f)) >= 0.1f;
    }

    // partitionable threefry, 32-bit: counter m (hi=0, lo=m), bits = v0 ^ v1
    unsigned m = (unsigned)(b * 1024 + i * 32 + j);
    unsigned v0, v1;
    threefry_0_42(0u, m, v0, v1);
    unsigned bits = v0 ^ v1;
    unsigned key = cand ? ((((bits >> 9) << 5) | (unsigned)(31 - j)) + 1u) : 0u;
    #pragma unroll
    for (int off = 16; off >= 1; off >>= 1) {
        unsigned o = __shfl_xor_sync(0xffffffffu, key, off);
        key = key > o ? key : o;
    }
    if (j == 0) {
        float c0 = 0.f, c1 = 0.f, c2 = 0.f;
        if (key) {
            int idx = 31 - (int)((key - 1u) & 31u);
            c0 = pos_coords[(b*II + idx)*3 + 0];
            c1 = pos_coords[(b*II + idx)*3 + 1];
            c2 = pos_coords[(b*II + idx)*3 + 2];
        }
        s_negc[i*3 + 0] = c0; s_negc[i*3 + 1] = c1; s_negc[i*3 + 2] = c2;
    }
    __syncthreads();

    // ped = pe - (tf32(negc) @ Wpr.T + bp)
    for (int idx = t; idx < II * EE; idx += 1024) {
        int ii = idx >> 7, e = idx & 127;
        float c0 = tf32r(s_negc[ii*3+0]);
        float c1 = tf32r(s_negc[ii*3+1]);
        float c2 = tf32r(s_negc[ii*3+2]);
        float ne = c0*d_Wpr[e*3] + c1*d_Wpr[e*3+1] + c2*d_Wpr[e*3+2] + bp[e];
        d_ped[b*II*EE + idx] = d_pe[b*II*EE + idx] - ne;
    }
}

// ---------------- launch ----------------
extern "C" void kernel_launch(void* const* d_in, const int* in_sizes, int n_in,
                              void* d_out, int out_size) {
    const float* points     = (const float*)d_in[0];
    const float* pos_coords = (const float*)d_in[1];
    const float* W1  = (const float*)d_in[2];
    const float* A1  = (const float*)d_in[3];
    const float* B1  = (const float*)d_in[4];
    const float* W2  = (const float*)d_in[5];
    const float* A2  = (const float*)d_in[6];
    const float* B2  = (const float*)d_in[7];
    const float* Wp  = (const float*)d_in[8];
    const float* bp  = (const float*)d_in[9];
    const float* Wd1 = (const float*)d_in[10];
    const float* bd1 = (const float*)d_in[11];
    const float* Wd2 = (const float*)d_in[12];
    const float* bd2 = (const float*)d_in[13];

    float* out = (float*)d_out;
    float* out_refined = out;                      // [2,32,8192]
    float* out_pf = out + (size_t)BB * II * NN;    // [2,8192,128]

    static float* d_pe_ptr = nullptr;
    static float* d_ped_ptr = nullptr;
    if (!d_pe_ptr)  cudaGetSymbolAddress((void**)&d_pe_ptr,  d_pe);
    if (!d_ped_ptr) cudaGetSymbolAddress((void**)&d_ped_ptr, d_ped);

    int smem_bytes = (128*XS_STR + EE*WD_STR + 128*WD_STR + 128 + 64 + 64) * 4;
    cudaFuncSetAttribute(k_decode, cudaFuncAttributeMaxDynamicSharedMemorySize, smem_bytes);

    k_setup<<<1, 1024>>>(W1, A1, B1, W2, A2, B2, Wp, bp, Wd1, Wd2, pos_coords);
    k_encoder<<<128, 128>>>(points, out_pf);
    dim3 dgrid(NN/128, II, BB);
    k_decode<<<dgrid, 128, smem_bytes>>>(out_pf, d_pe_ptr, bd1, bd2, 0, nullptr);
    k_sample<<<BB, 1024>>>(pos_coords, bp);
    k_decode<<<dgrid, 128, smem_bytes>>>(out_pf, d_ped_ptr, bd1, bd2, 1, out_refined);
}

// round 12
// speedup vs baseline: 2.6918x; 2.6918x over previous
#include <cuda_runtime.h>

#define BB 2
#define NN 8192
#define II 32
#define EE 128
#define HH 64
#define NW (NN/32)

// ---------------- device scratch ----------------
__device__ float d_W1r[HH*3];
__device__ float d_A1r[12];
__device__ float d_B1r[HH*4];
__device__ float d_W2r[EE*HH];     // [e][c]
__device__ float d_A2r[4*HH];      // [r][c]
__device__ float d_B2r[EE*4];      // [e][r]
__device__ float d_Wpr[EE*3];      // [e][j]
__device__ float d_Wd2r[HH];
__device__ float2 d_Wd1p[16*8*32]; // B fragments: [chunk][ktile][lane] = (wd1t[e][k], wd1t[e+4][k])
__device__ float d_pe[BB*II*EE];
__device__ float d_ped[BB*II*EE];  // pe - neg_embed
__device__ unsigned d_mask[BB*II*NW];
__device__ int d_inter[BB*II*II];

// TF32 round-to-nearest (matches cublas input rounding)
__device__ __forceinline__ float tf32r(float x) {
    float y;
    asm("cvt.rna.tf32.f32 %0, %1;" : "=f"(y) : "f"(x));
    return y;
}

// ---------------- threefry2x32, key=(0,42) ----------------
__device__ __forceinline__ void threefry_0_42(unsigned x0, unsigned x1,
                                              unsigned& o0, unsigned& o1) {
    const unsigned k0 = 0u, k1 = 42u;
    const unsigned k2 = 0x1BD11BDAu ^ k0 ^ k1;
    unsigned v0 = x0 + k0, v1 = x1 + k1;
#define TF_R(r) { v0 += v1; v1 = (v1 << (r)) | (v1 >> (32 - (r))); v1 ^= v0; }
    TF_R(13) TF_R(15) TF_R(26) TF_R(6)   v0 += k1; v1 += k2 + 1u;
    TF_R(17) TF_R(29) TF_R(16) TF_R(24)  v0 += k2; v1 += k0 + 2u;
    TF_R(13) TF_R(15) TF_R(26) TF_R(6)   v0 += k0; v1 += k1 + 3u;
    TF_R(17) TF_R(29) TF_R(16) TF_R(24)  v0 += k1; v1 += k2 + 4u;
    TF_R(13) TF_R(15) TF_R(26) TF_R(6)   v0 += k2; v1 += k0 + 5u;
#undef TF_R
    o0 = v0; o1 = v1;
}

// ---------------- K0: round weights + pos_embed + pack Wd1 fragments ----------------
__global__ void k_setup(const float* __restrict__ W1, const float* __restrict__ A1,
                        const float* __restrict__ B1, const float* __restrict__ W2,
                        const float* __restrict__ A2, const float* __restrict__ B2,
                        const float* __restrict__ Wp, const float* __restrict__ bp,
                        const float* __restrict__ Wd1, const float* __restrict__ Wd2,
                        const float* __restrict__ pos_coords) {
    int t = threadIdx.x;
    for (int i = t; i < HH*3;  i += 1024) d_W1r[i] = tf32r(W1[i]);
    for (int i = t; i < 12;    i += 1024) d_A1r[i] = tf32r(A1[i]);
    for (int i = t; i < HH*4;  i += 1024) d_B1r[i] = tf32r(B1[i]);
    for (int i = t; i < EE*HH; i += 1024) d_W2r[i] = tf32r(W2[i]);
    for (int i = t; i < 4*HH;  i += 1024) d_A2r[i] = tf32r(A2[i]);
    for (int i = t; i < EE*4;  i += 1024) d_B2r[i] = tf32r(B2[i]);
    for (int i = t; i < EE*3;  i += 1024) d_Wpr[i] = tf32r(Wp[i]);
    for (int i = t; i < HH;    i += 1024) d_Wd2r[i] = tf32r(Wd2[i]);
    // pack wd1t[e][k] = tf32r(Wd1[k*EE+e]) into mma B fragments
    // b0: e = ch*8 + lane%4, k = tl*8 + lane/4 ; b1: e+4
    for (int i = t; i < 16*8*32; i += 1024) {
        int ch = i >> 8, tl = (i >> 5) & 7, ln = i & 31;
        int e0 = ch*8 + (ln & 3);
        int k  = tl*8 + (ln >> 2);
        d_Wd1p[i] = make_float2(tf32r(Wd1[k*EE + e0]), tf32r(Wd1[k*EE + e0 + 4]));
    }
    __syncthreads();
    // pos_embed = tf32(pos) @ Wpr.T + bp
    for (int i = t; i < BB*II*EE; i += 1024) {
        int bi = i >> 7, e = i & 127;
        float p0 = tf32r(pos_coords[bi*3+0]);
        float p1 = tf32r(pos_coords[bi*3+1]);
        float p2 = tf32r(pos_coords[bi*3+2]);
        d_pe[i] = p0*d_Wpr[e*3] + p1*d_Wpr[e*3+1] + p2*d_Wpr[e*3+2] + bp[e];
    }
}

// ---------------- K1: encoder (TF32-emulated LoRA chain) — UNCHANGED numerics ----------------
__global__ __launch_bounds__(128) void k_encoder(const float* __restrict__ points,
                                                 float* __restrict__ out_pf) {
    __shared__ float sW2r[EE*HH];
    __shared__ float sB2r[EE*4];
    __shared__ float sW1r[HH*3];
    __shared__ float sA1r[12];
    __shared__ float sB1r[HH*4];
    __shared__ float sA2r[4*HH];
    int t = threadIdx.x;
    for (int i = t; i < EE*HH; i += 128) sW2r[i] = d_W2r[i];
    for (int i = t; i < EE*4;  i += 128) sB2r[i] = d_B2r[i];
    for (int i = t; i < HH*3;  i += 128) sW1r[i] = d_W1r[i];
    for (int i = t; i < 12;    i += 128) sA1r[i] = d_A1r[i];
    for (int i = t; i < HH*4;  i += 128) sB1r[i] = d_B1r[i];
    for (int i = t; i < 4*HH;  i += 128) sA2r[i] = d_A2r[i];
    __syncthreads();

    int m = blockIdx.x * 128 + t;
    float p0 = tf32r(points[m*3]), p1 = tf32r(points[m*3+1]), p2 = tf32r(points[m*3+2]);

    float ur[4];
    #pragma unroll
    for (int r = 0; r < 4; r++)
        ur[r] = tf32r(p0*sA1r[r*3] + p1*sA1r[r*3+1] + p2*sA1r[r*3+2]);

    float h1r[HH];
    #pragma unroll 4
    for (int c = 0; c < HH; c++) {
        float t1 = p0*sW1r[c*3] + p1*sW1r[c*3+1] + p2*sW1r[c*3+2];
        float l1 = ur[0]*sB1r[c*4] + ur[1]*sB1r[c*4+1] + ur[2]*sB1r[c*4+2] + ur[3]*sB1r[c*4+3];
        float h = t1 + 0.25f*l1;
        h1r[c] = tf32r(fmaxf(h, 0.f));
    }

    float vr[4];
    #pragma unroll
    for (int r = 0; r < 4; r++) {
        float s = 0.f;
        #pragma unroll 8
        for (int c = 0; c < HH; c++) s += h1r[c]*sA2r[r*HH + c];
        vr[r] = tf32r(s);
    }

    float4* pout = (float4*)(out_pf + (size_t)m * EE);
    #pragma unroll 2
    for (int e4 = 0; e4 < 32; e4++) {
        float o[4];
        #pragma unroll
        for (int q = 0; q < 4; q++) {
            int e = e4*4 + q;
            float s = 0.f;
            #pragma unroll 8
            for (int c = 0; c < HH; c++) s += h1r[c]*sW2r[e*HH + c];
            float l2 = vr[0]*sB2r[e*4] + vr[1]*sB2r[e*4+1] + vr[2]*sB2r[e*4+2] + vr[3]*sB2r[e*4+3];
            o[q] = s + 0.25f*l2;
        }
        pout[e4] = make_float4(o[0], o[1], o[2], o[3]);
    }
}

// ---------------- K2/K4: tensor-core TF32 decode ----------------
// grid (ntile=64, b=2), 256 threads (8 warps). Loops all 32 prompts with
// pf-tile xs staged in smem. mode 0: mask ballots; mode 1: refined logits.
#define XSTR 132
__global__ __launch_bounds__(256) void k_decode_mma(const float* __restrict__ pf,
                                                    const float* __restrict__ pesrc,
                                                    const float* __restrict__ bd1,
                                                    const float* __restrict__ bd2,
                                                    int mode, float* __restrict__ out) {
    extern __shared__ float sm[];
    float* xs   = sm;                 // [128][XSTR]
    float* swb  = xs + 128*XSTR;      // 4096 float2 = 8192 floats
    float* sbd1 = swb + 8192;         // 64
    float* sw2  = sbd1 + 64;          // 64
    float* slg  = sw2 + 64;           // 128

    int t = threadIdx.x;
    int ntile = blockIdx.x, b = blockIdx.y;
    int base = ntile * 128;
    int lane = t & 31, w = t >> 5;

    {
        float2* swb2 = (float2*)swb;
        for (int i = t; i < 4096; i += 256) swb2[i] = d_Wd1p[i];
        if (t < 64) { sbd1[t] = bd1[t]; sw2[t] = d_Wd2r[t]; }
    }
    float bd2v = bd2[0];
    __syncthreads();

    const float4* pfb = (const float4*)(pf + ((size_t)(b*NN + base)) * EE);
    const float* xrow = xs + (w*16 + (lane >> 2)) * XSTR + (lane & 3);

    for (int i = 0; i < II; i++) {
        // phase A: xs = tf32r(pf + pe_i)
        const float4* pe4 = (const float4*)(pesrc + (size_t)(b*II + i) * EE);
        #pragma unroll
        for (int q = 0; q < 16; q++) {
            int idx4 = t + 256*q;
            int n = idx4 >> 5, e4 = idx4 & 31;
            float4 pv = __ldg(&pfb[n*32 + e4]);
            float4 qv = __ldg(&pe4[e4]);
            float4 xv;
            xv.x = tf32r(pv.x + qv.x); xv.y = tf32r(pv.y + qv.y);
            xv.z = tf32r(pv.z + qv.z); xv.w = tf32r(pv.w + qv.w);
            *(float4*)&xs[n*XSTR + e4*4] = xv;
        }
        __syncthreads();

        // phase B: hidden = xs @ wd1 via m16n8k8 tf32 MMA, K=128 in 16 chunks
        float acc[8][4];
        #pragma unroll
        for (int tl = 0; tl < 8; tl++) {
            acc[tl][0] = 0.f; acc[tl][1] = 0.f; acc[tl][2] = 0.f; acc[tl][3] = 0.f;
        }
        #pragma unroll
        for (int ch = 0; ch < 16; ch++) {
            unsigned a0 = __float_as_uint(xrow[ch*8]);
            unsigned a1 = __float_as_uint(xrow[8*XSTR + ch*8]);
            unsigned a2 = __float_as_uint(xrow[ch*8 + 4]);
            unsigned a3 = __float_as_uint(xrow[8*XSTR + ch*8 + 4]);
            #pragma unroll
            for (int tl = 0; tl < 8; tl++) {
                float2 bb = ((float2*)swb)[(ch*8 + tl)*32 + lane];
                unsigned b0 = __float_as_uint(bb.x), b1 = __float_as_uint(bb.y);
                asm volatile(
                    "mma.sync.aligned.m16n8k8.row.col.f32.tf32.tf32.f32 "
                    "{%0,%1,%2,%3}, {%4,%5,%6,%7}, {%8,%9}, {%0,%1,%2,%3};"
                    : "+f"(acc[tl][0]), "+f"(acc[tl][1]), "+f"(acc[tl][2]), "+f"(acc[tl][3])
                    : "r"(a0), "r"(a1), "r"(a2), "r"(a3), "r"(b0), "r"(b1));
            }
        }

        // phase C: relu+bias+round, dot with w2, reduce across the 4-lane group
        float p0 = 0.f, p1 = 0.f;
        #pragma unroll
        for (int tl = 0; tl < 8; tl++) {
            int k0 = tl*8 + 2*(lane & 3);
            float h;
            h = tf32r(fmaxf(acc[tl][0] + sbd1[k0],   0.f)); p0 += h * sw2[k0];
            h = tf32r(fmaxf(acc[tl][1] + sbd1[k0+1], 0.f)); p0 += h * sw2[k0+1];
            h = tf32r(fmaxf(acc[tl][2] + sbd1[k0],   0.f)); p1 += h * sw2[k0];
            h = tf32r(fmaxf(acc[tl][3] + sbd1[k0+1], 0.f)); p1 += h * sw2[k0+1];
        }
        p0 += __shfl_xor_sync(0xffffffffu, p0, 1);
        p0 += __shfl_xor_sync(0xffffffffu, p0, 2);
        p1 += __shfl_xor_sync(0xffffffffu, p1, 1);
        p1 += __shfl_xor_sync(0xffffffffu, p1, 2);
        if ((lane & 3) == 0) {
            slg[w*16 + (lane >> 2)]     = bd2v + p0;
            slg[w*16 + (lane >> 2) + 8] = bd2v + p1;
        }
        __syncthreads();

        // phase D: emit
        if (mode == 0) {
            if (t < 128) {
                unsigned ball = __ballot_sync(0xffffffffu, slg[t] > 0.f);
                if ((t & 31) == 0)
                    d_mask[(b*II + i)*NW + (base >> 5) + (t >> 5)] = ball;
            }
        } else {
            if (t < 128)
                out[((size_t)(b*II + i))*NN + base + t] = slg[t];
        }
        __syncthreads();
    }
}

// ---------------- K3a: pairwise mask intersections (L2-resident) ----------------
__global__ __launch_bounds__(256) void k_inter() {
    __shared__ unsigned smi[NW];
    int blk = blockIdx.x;            // b*II + i
    int b = blk >> 5;
    int t = threadIdx.x, lane = t & 31, w = t >> 5;
    const unsigned* mi = d_mask + (size_t)blk * NW;
    if (t < NW) smi[t] = mi[t];
    __syncthreads();
    for (int j = w; j < II; j += 8) {
        const unsigned* mj = d_mask + (size_t)(b*II + j) * NW;
        int cnt = 0;
        #pragma unroll
        for (int q = 0; q < 8; q++) {
            int idx = lane + 32*q;
            cnt += __popc(smi[idx] & mj[idx]);
        }
        #pragma unroll
        for (int off = 16; off >= 1; off >>= 1)
            cnt += __shfl_xor_sync(0xffffffffu, cnt, off);
        if (lane == 0) d_inter[blk*II + j] = cnt;
    }
}

// ---------------- K3b: gumbel-max pick + (pe - neg_embed) — logic unchanged ----------------
__global__ __launch_bounds__(1024) void k_pick(const float* __restrict__ pos_coords,
                                               const float* __restrict__ bp) {
    __shared__ float s_negc[II * 3];
    int b = blockIdx.x;
    int t = threadIdx.x;
    int i = t >> 5, j = t & 31;

    int cnt_ij = d_inter[b*II*II + i*II + j];
    int cnt_ii = d_inter[b*II*II + i*II + i];
    int cnt_jj = d_inter[b*II*II + j*II + j];

    bool cand = false;
    if (i != j) {
        float inter = (float)cnt_ij;
        float uni = (float)(cnt_ii + cnt_jj) - inter;
        cand = (inter / (uni + 1e-6f)) >= 0.1f;
    }

    // partitionable threefry, 32-bit: counter m (hi=0, lo=m), bits = v0 ^ v1
    unsigned m = (unsigned)(b * 1024 + i * 32 + j);
    unsigned v0, v1;
    threefry_0_42(0u, m, v0, v1);
    unsigned bits = v0 ^ v1;
    unsigned key = cand ? ((((bits >> 9) << 5) | (unsigned)(31 - j)) + 1u) : 0u;
    #pragma unroll
    for (int off = 16; off >= 1; off >>= 1) {
        unsigned o = __shfl_xor_sync(0xffffffffu, key, off);
        key = key > o ? key : o;
    }
    if (j == 0) {
        float c0 = 0.f, c1 = 0.f, c2 = 0.f;
        if (key) {
            int idx = 31 - (int)((key - 1u) & 31u);
            c0 = pos_coords[(b*II + idx)*3 + 0];
            c1 = pos_coords[(b*II + idx)*3 + 1];
            c2 = pos_coords[(b*II + idx)*3 + 2];
        }
        s_negc[i*3 + 0] = c0; s_negc[i*3 + 1] = c1; s_negc[i*3 + 2] = c2;
    }
    __syncthreads();

    // ped = pe - (tf32(negc) @ Wpr.T + bp)
    for (int idx = t; idx < II * EE; idx += 1024) {
        int ii = idx >> 7, e = idx & 127;
        float c0 = tf32r(s_negc[ii*3+0]);
        float c1 = tf32r(s_negc[ii*3+1]);
        float c2 = tf32r(s_negc[ii*3+2]);
        float ne = c0*d_Wpr[e*3] + c1*d_Wpr[e*3+1] + c2*d_Wpr[e*3+2] + bp[e];
        d_ped[b*II*EE + idx] = d_pe[b*II*EE + idx] - ne;
    }
}

// ---------------- launch ----------------
extern "C" void kernel_launch(void* const* d_in, const int* in_sizes, int n_in,
                              void* d_out, int out_size) {
    const float* points     = (const float*)d_in[0];
    const float* pos_coords = (const float*)d_in[1];
    const float* W1  = (const float*)d_in[2];
    const float* A1  = (const float*)d_in[3];
    const float* B1  = (const float*)d_in[4];
    const float* W2  = (const float*)d_in[5];
    const float* A2  = (const float*)d_in[6];
    const float* B2  = (const float*)d_in[7];
    const float* Wp  = (const float*)d_in[8];
    const float* bp  = (const float*)d_in[9];
    const float* Wd1 = (const float*)d_in[10];
    const float* bd1 = (const float*)d_in[11];
    const float* Wd2 = (const float*)d_in[12];
    const float* bd2 = (const float*)d_in[13];

    float* out = (float*)d_out;
    float* out_refined = out;                      // [2,32,8192]
    float* out_pf = out + (size_t)BB * II * NN;    // [2,8192,128]

    static float* d_pe_ptr = nullptr;
    static float* d_ped_ptr = nullptr;
    if (!d_pe_ptr)  cudaGetSymbolAddress((void**)&d_pe_ptr,  d_pe);
    if (!d_ped_ptr) cudaGetSymbolAddress((void**)&d_ped_ptr, d_ped);

    int smem_bytes = (128*XSTR + 8192 + 64 + 64 + 128) * 4;
    cudaFuncSetAttribute(k_decode_mma, cudaFuncAttributeMaxDynamicSharedMemorySize, smem_bytes);

    k_setup<<<1, 1024>>>(W1, A1, B1, W2, A2, B2, Wp, bp, Wd1, Wd2, pos_coords);
    k_encoder<<<128, 128>>>(points, out_pf);
    dim3 dgrid(NN/128, BB);
    k_decode_mma<<<dgrid, 256, smem_bytes>>>(out_pf, d_pe_ptr, bd1, bd2, 0, nullptr);
    k_inter<<<BB*II, 256>>>();
    k_pick<<<BB, 1024>>>(pos_coords, bp);
    k_decode_mma<<<dgrid, 256, smem_bytes>>>(out_pf, d_ped_ptr, bd1, bd2, 1, out_refined);
}

// round 15
// speedup vs baseline: 3.2127x; 1.1935x over previous
#include <cuda_runtime.h>

#define BB 2
#define NN 8192
#define II 32
#define EE 128
#define HH 64
#define NW (NN/32)

// ---------------- device scratch ----------------
__device__ float d_W1r[HH*3];
__device__ float d_A1r[12];
__device__ float d_B1r[HH*4];
__device__ float d_W2r[EE*HH];     // [e][c]
__device__ float d_A2r[4*HH];      // [r][c]
__device__ float d_B2r[EE*4];      // [e][r]
__device__ float d_Wpr[EE*3];      // [e][j]
__device__ float d_Wd2r[HH];
__device__ float2 d_Wd1p[16*8*32]; // B fragments: [chunk][ktile][lane]
__device__ float d_pe[BB*II*EE];
__device__ float d_ped[BB*II*EE];  // pe - neg_embed
__device__ unsigned d_mask[BB*II*NW];
__device__ int d_inter[BB*II*II];

// TF32 round-to-nearest (matches cublas input rounding)
__device__ __forceinline__ float tf32r(float x) {
    float y;
    asm("cvt.rna.tf32.f32 %0, %1;" : "=f"(y) : "f"(x));
    return y;
}

// ---------------- threefry2x32, key=(0,42) ----------------
__device__ __forceinline__ void threefry_0_42(unsigned x0, unsigned x1,
                                              unsigned& o0, unsigned& o1) {
    const unsigned k0 = 0u, k1 = 42u;
    const unsigned k2 = 0x1BD11BDAu ^ k0 ^ k1;
    unsigned v0 = x0 + k0, v1 = x1 + k1;
#define TF_R(r) { v0 += v1; v1 = (v1 << (r)) | (v1 >> (32 - (r))); v1 ^= v0; }
    TF_R(13) TF_R(15) TF_R(26) TF_R(6)   v0 += k1; v1 += k2 + 1u;
    TF_R(17) TF_R(29) TF_R(16) TF_R(24)  v0 += k2; v1 += k0 + 2u;
    TF_R(13) TF_R(15) TF_R(26) TF_R(6)   v0 += k0; v1 += k1 + 3u;
    TF_R(17) TF_R(29) TF_R(16) TF_R(24)  v0 += k1; v1 += k2 + 4u;
    TF_R(13) TF_R(15) TF_R(26) TF_R(6)   v0 += k2; v1 += k0 + 5u;
#undef TF_R
    o0 = v0; o1 = v1;
}

// ---------------- K0: round weights + pos_embed + pack Wd1 fragments ----------------
__global__ void k_setup(const float* __restrict__ W1, const float* __restrict__ A1,
                        const float* __restrict__ B1, const float* __restrict__ W2,
                        const float* __restrict__ A2, const float* __restrict__ B2,
                        const float* __restrict__ Wp, const float* __restrict__ bp,
                        const float* __restrict__ Wd1, const float* __restrict__ Wd2,
                        const float* __restrict__ pos_coords) {
    int t = threadIdx.x;
    for (int i = t; i < HH*3;  i += 1024) d_W1r[i] = tf32r(W1[i]);
    for (int i = t; i < 12;    i += 1024) d_A1r[i] = tf32r(A1[i]);
    for (int i = t; i < HH*4;  i += 1024) d_B1r[i] = tf32r(B1[i]);
    for (int i = t; i < EE*HH; i += 1024) d_W2r[i] = tf32r(W2[i]);
    for (int i = t; i < 4*HH;  i += 1024) d_A2r[i] = tf32r(A2[i]);
    for (int i = t; i < EE*4;  i += 1024) d_B2r[i] = tf32r(B2[i]);
    for (int i = t; i < EE*3;  i += 1024) d_Wpr[i] = tf32r(Wp[i]);
    for (int i = t; i < HH;    i += 1024) d_Wd2r[i] = tf32r(Wd2[i]);
    for (int i = t; i < 16*8*32; i += 1024) {
        int ch = i >> 8, tl = (i >> 5) & 7, ln = i & 31;
        int e0 = ch*8 + (ln & 3);
        int k  = tl*8 + (ln >> 2);
        d_Wd1p[i] = make_float2(tf32r(Wd1[k*EE + e0]), tf32r(Wd1[k*EE + e0 + 4]));
    }
    __syncthreads();
    for (int i = t; i < BB*II*EE; i += 1024) {
        int bi = i >> 7, e = i & 127;
        float p0 = tf32r(pos_coords[bi*3+0]);
        float p1 = tf32r(pos_coords[bi*3+1]);
        float p2 = tf32r(pos_coords[bi*3+2]);
        d_pe[i] = p0*d_Wpr[e*3] + p1*d_Wpr[e*3+1] + p2*d_Wpr[e*3+2] + bp[e];
    }
}

// ---------------- K1: encoder (TF32-emulated LoRA chain) — UNCHANGED ----------------
__global__ __launch_bounds__(128) void k_encoder(const float* __restrict__ points,
                                                 float* __restrict__ out_pf) {
    __shared__ float sW2r[EE*HH];
    __shared__ float sB2r[EE*4];
    __shared__ float sW1r[HH*3];
    __shared__ float sA1r[12];
    __shared__ float sB1r[HH*4];
    __shared__ float sA2r[4*HH];
    int t = threadIdx.x;
    for (int i = t; i < EE*HH; i += 128) sW2r[i] = d_W2r[i];
    for (int i = t; i < EE*4;  i += 128) sB2r[i] = d_B2r[i];
    for (int i = t; i < HH*3;  i += 128) sW1r[i] = d_W1r[i];
    for (int i = t; i < 12;    i += 128) sA1r[i] = d_A1r[i];
    for (int i = t; i < HH*4;  i += 128) sB1r[i] = d_B1r[i];
    for (int i = t; i < 4*HH;  i += 128) sA2r[i] = d_A2r[i];
    __syncthreads();

    int m = blockIdx.x * 128 + t;
    float p0 = tf32r(points[m*3]), p1 = tf32r(points[m*3+1]), p2 = tf32r(points[m*3+2]);

    float ur[4];
    #pragma unroll
    for (int r = 0; r < 4; r++)
        ur[r] = tf32r(p0*sA1r[r*3] + p1*sA1r[r*3+1] + p2*sA1r[r*3+2]);

    float h1r[HH];
    #pragma unroll 4
    for (int c = 0; c < HH; c++) {
        float t1 = p0*sW1r[c*3] + p1*sW1r[c*3+1] + p2*sW1r[c*3+2];
        float l1 = ur[0]*sB1r[c*4] + ur[1]*sB1r[c*4+1] + ur[2]*sB1r[c*4+2] + ur[3]*sB1r[c*4+3];
        float h = t1 + 0.25f*l1;
        h1r[c] = tf32r(fmaxf(h, 0.f));
    }

    float vr[4];
    #pragma unroll
    for (int r = 0; r < 4; r++) {
        float s = 0.f;
        #pragma unroll 8
        for (int c = 0; c < HH; c++) s += h1r[c]*sA2r[r*HH + c];
        vr[r] = tf32r(s);
    }

    float4* pout = (float4*)(out_pf + (size_t)m * EE);
    #pragma unroll 2
    for (int e4 = 0; e4 < 32; e4++) {
        float o[4];
        #pragma unroll
        for (int q = 0; q < 4; q++) {
            int e = e4*4 + q;
            float s = 0.f;
            #pragma unroll 8
            for (int c = 0; c < HH; c++) s += h1r[c]*sW2r[e*HH + c];
            float l2 = vr[0]*sB2r[e*4] + vr[1]*sB2r[e*4+1] + vr[2]*sB2r[e*4+2] + vr[3]*sB2r[e*4+3];
            o[q] = s + 0.25f*l2;
        }
        pout[e4] = make_float4(o[0], o[1], o[2], o[3]);
    }
}

// ---------------- K2/K4: tensor-core TF32 decode, pf in registers ----------------
// grid (ntile=64, b=2), 256 threads (8 warps). A-fragments built on the fly
// from per-thread pf registers + smem pe rows; values bit-identical to R12.
__global__ __launch_bounds__(256) void k_decode_mma(const float* __restrict__ pf,
                                                    const float* __restrict__ pesrc,
                                                    const float* __restrict__ bd1,
                                                    const float* __restrict__ bd2,
                                                    int mode, float* __restrict__ out) {
    extern __shared__ float sm[];
    float* swb  = sm;                 // 4096 float2 = 8192 floats (32KB)
    float* spe  = swb + 8192;         // [32][128] pe rows (16KB)
    float* sbd1 = spe + II*EE;        // 64
    float* sw2  = sbd1 + 64;          // 64
    float* slg  = sw2 + 64;           // 128

    int t = threadIdx.x;
    int ntile = blockIdx.x, b = blockIdx.y;
    int base = ntile * 128;
    int lane = t & 31, w = t >> 5;

    {
        float2* swb2 = (float2*)swb;
        #pragma unroll 4
        for (int i = t; i < 4096; i += 256) swb2[i] = d_Wd1p[i];
        const float4* pesrc4 = (const float4*)(pesrc + (size_t)b*II*EE);
        float4* spe4 = (float4*)spe;
        #pragma unroll 4
        for (int i = t; i < II*EE/4; i += 256) spe4[i] = pesrc4[i];
        if (t < 64) { sbd1[t] = bd1[t]; sw2[t] = d_Wd2r[t]; }
    }
    float bd2v = bd2[0];

    // pf A-fragment registers: rows n1, n1+8; cols (lane&3)+8ch, +4
    int n1 = base + w*16 + (lane >> 2);
    const float* pf1 = pf + ((size_t)(b*NN) + n1) * EE;
    const float* pf2 = pf1 + 8*EE;
    int c0b = lane & 3;
    float pa[16], pb[16], pc[16], pd[16];
    #pragma unroll
    for (int ch = 0; ch < 16; ch++) {
        int c0 = c0b + 8*ch;
        pa[ch] = __ldg(pf1 + c0);
        pb[ch] = __ldg(pf2 + c0);
        pc[ch] = __ldg(pf1 + c0 + 4);
        pd[ch] = __ldg(pf2 + c0 + 4);
    }
    __syncthreads();

    for (int i = 0; i < II; i++) {
        const float* pei = spe + i*EE;
        float acc[8][4];
        #pragma unroll
        for (int tl = 0; tl < 8; tl++) {
            acc[tl][0] = 0.f; acc[tl][1] = 0.f; acc[tl][2] = 0.f; acc[tl][3] = 0.f;
        }
        #pragma unroll
        for (int ch = 0; ch < 16; ch++) {
            float peA = pei[c0b + 8*ch];
            float peB = pei[c0b + 8*ch + 4];
            unsigned a0 = __float_as_uint(tf32r(pa[ch] + peA));
            unsigned a1 = __float_as_uint(tf32r(pb[ch] + peA));
            unsigned a2 = __float_as_uint(tf32r(pc[ch] + peB));
            unsigned a3 = __float_as_uint(tf32r(pd[ch] + peB));
            #pragma unroll
            for (int tl = 0; tl < 8; tl++) {
                float2 bb = ((float2*)swb)[(ch*8 + tl)*32 + lane];
                unsigned b0 = __float_as_uint(bb.x), b1 = __float_as_uint(bb.y);
                asm volatile(
                    "mma.sync.aligned.m16n8k8.row.col.f32.tf32.tf32.f32 "
                    "{%0,%1,%2,%3}, {%4,%5,%6,%7}, {%8,%9}, {%0,%1,%2,%3};"
                    : "+f"(acc[tl][0]), "+f"(acc[tl][1]), "+f"(acc[tl][2]), "+f"(acc[tl][3])
                    : "r"(a0), "r"(a1), "r"(a2), "r"(a3), "r"(b0), "r"(b1));
            }
        }

        // epilogue — identical to R12
        float p0 = 0.f, p1 = 0.f;
        #pragma unroll
        for (int tl = 0; tl < 8; tl++) {
            int k0 = tl*8 + 2*(lane & 3);
            float h;
            h = tf32r(fmaxf(acc[tl][0] + sbd1[k0],   0.f)); p0 += h * sw2[k0];
            h = tf32r(fmaxf(acc[tl][1] + sbd1[k0+1], 0.f)); p0 += h * sw2[k0+1];
            h = tf32r(fmaxf(acc[tl][2] + sbd1[k0],   0.f)); p1 += h * sw2[k0];
            h = tf32r(fmaxf(acc[tl][3] + sbd1[k0+1], 0.f)); p1 += h * sw2[k0+1];
        }
        p0 += __shfl_xor_sync(0xffffffffu, p0, 1);
        p0 += __shfl_xor_sync(0xffffffffu, p0, 2);
        p1 += __shfl_xor_sync(0xffffffffu, p1, 1);
        p1 += __shfl_xor_sync(0xffffffffu, p1, 2);
        if ((lane & 3) == 0) {
            slg[w*16 + (lane >> 2)]     = bd2v + p0;
            slg[w*16 + (lane >> 2) + 8] = bd2v + p1;
        }
        __syncthreads();

        if (mode == 0) {
            if (t < 128) {
                unsigned ball = __ballot_sync(0xffffffffu, slg[t] > 0.f);
                if ((t & 31) == 0)
                    d_mask[(b*II + i)*NW + (base >> 5) + (t >> 5)] = ball;
            }
        } else {
            if (t < 128)
                out[((size_t)(b*II + i))*NN + base + t] = slg[t];
        }
        __syncthreads();
    }
}

// ---------------- K3a: pairwise mask intersections ----------------
__global__ __launch_bounds__(256) void k_inter() {
    __shared__ unsigned smi[NW];
    int blk = blockIdx.x;            // b*II + i
    int b = blk >> 5;
    int t = threadIdx.x, lane = t & 31, w = t >> 5;
    const unsigned* mi = d_mask + (size_t)blk * NW;
    if (t < NW) smi[t] = mi[t];
    __syncthreads();
    for (int j = w; j < II; j += 8) {
        const unsigned* mj = d_mask + (size_t)(b*II + j) * NW;
        int cnt = 0;
        #pragma unroll
        for (int q = 0; q < 8; q++) {
            int idx = lane + 32*q;
            cnt += __popc(smi[idx] & mj[idx]);
        }
        #pragma unroll
        for (int off = 16; off >= 1; off >>= 1)
            cnt += __shfl_xor_sync(0xffffffffu, cnt, off);
        if (lane == 0) d_inter[blk*II + j] = cnt;
    }
}

// ---------------- K3b: gumbel-max pick + (pe - neg_embed) ----------------
__global__ __launch_bounds__(1024) void k_pick(const float* __restrict__ pos_coords,
                                               const float* __restrict__ bp) {
    __shared__ float s_negc[II * 3];
    int b = blockIdx.x;
    int t = threadIdx.x;
    int i = t >> 5, j = t & 31;

    int cnt_ij = d_inter[b*II*II + i*II + j];
    int cnt_ii = d_inter[b*II*II + i*II + i];
    int cnt_jj = d_inter[b*II*II + j*II + j];

    bool cand = false;
    if (i != j) {
        float inter = (float)cnt_ij;
        float uni = (float)(cnt_ii + cnt_jj) - inter;
        cand = (inter / (uni + 1e-6f)) >= 0.1f;
    }

    unsigned m = (unsigned)(b * 1024 + i * 32 + j);
    unsigned v0, v1;
    threefry_0_42(0u, m, v0, v1);
    unsigned bits = v0 ^ v1;
    unsigned key = cand ? ((((bits >> 9) << 5) | (unsigned)(31 - j)) + 1u) : 0u;
    #pragma unroll
    for (int off = 16; off >= 1; off >>= 1) {
        unsigned o = __shfl_xor_sync(0xffffffffu, key, off);
        key = key > o ? key : o;
    }
    if (j == 0) {
        float c0 = 0.f, c1 = 0.f, c2 = 0.f;
        if (key) {
            int idx = 31 - (int)((key - 1u) & 31u);
            c0 = pos_coords[(b*II + idx)*3 + 0];
            c1 = pos_coords[(b*II + idx)*3 + 1];
            c2 = pos_coords[(b*II + idx)*3 + 2];
        }
        s_negc[i*3 + 0] = c0; s_negc[i*3 + 1] = c1; s_negc[i*3 + 2] = c2;
    }
    __syncthreads();

    for (int idx = t; idx < II * EE; idx += 1024) {
        int ii = idx >> 7, e = idx & 127;
        float c0 = tf32r(s_negc[ii*3+0]);
        float c1 = tf32r(s_negc[ii*3+1]);
        float c2 = tf32r(s_negc[ii*3+2]);
        float ne = c0*d_Wpr[e*3] + c1*d_Wpr[e*3+1] + c2*d_Wpr[e*3+2] + bp[e];
        d_ped[b*II*EE + idx] = d_pe[b*II*EE + idx] - ne;
    }
}

// ---------------- launch ----------------
extern "C" void kernel_launch(void* const* d_in, const int* in_sizes, int n_in,
                              void* d_out, int out_size) {
    const float* points     = (const float*)d_in[0];
    const float* pos_coords = (const float*)d_in[1];
    const float* W1  = (const float*)d_in[2];
    const float* A1  = (const float*)d_in[3];
    const float* B1  = (const float*)d_in[4];
    const float* W2  = (const float*)d_in[5];
    const float* A2  = (const float*)d_in[6];
    const float* B2  = (const float*)d_in[7];
    const float* Wp  = (const float*)d_in[8];
    const float* bp  = (const float*)d_in[9];
    const float* Wd1 = (const float*)d_in[10];
    const float* bd1 = (const float*)d_in[11];
    const float* Wd2 = (const float*)d_in[12];
    const float* bd2 = (const float*)d_in[13];

    float* out = (float*)d_out;
    float* out_refined = out;                      // [2,32,8192]
    float* out_pf = out + (size_t)BB * II * NN;    // [2,8192,128]

    static float* d_pe_ptr = nullptr;
    static float* d_ped_ptr = nullptr;
    if (!d_pe_ptr)  cudaGetSymbolAddress((void**)&d_pe_ptr,  d_pe);
    if (!d_ped_ptr) cudaGetSymbolAddress((void**)&d_ped_ptr, d_ped);

    int smem_bytes = (8192 + II*EE + 64 + 64 + 128) * 4;
    cudaFuncSetAttribute(k_decode_mma, cudaFuncAttributeMaxDynamicSharedMemorySize, smem_bytes);

    k_setup<<<1, 1024>>>(W1, A1, B1, W2, A2, B2, Wp, bp, Wd1, Wd2, pos_coords);
    k_encoder<<<128, 128>>>(points, out_pf);
    dim3 dgrid(NN/128, BB);
    k_decode_mma<<<dgrid, 256, smem_bytes>>>(out_pf, d_pe_ptr, bd1, bd2, 0, nullptr);
    k_inter<<<BB*II, 256>>>();
    k_pick<<<BB, 1024>>>(pos_coords, bp);
    k_decode_mma<<<dgrid, 256, smem_bytes>>>(out_pf, d_ped_ptr, bd1, bd2, 1, out_refined);
}

// round 17
// speedup vs baseline: 3.2592x; 1.0145x over previous
#include <cuda_runtime.h>

#define BB 2
#define NN 8192
#define II 32
#define EE 128
#define HH 64
#define NW (NN/32)

// ---------------- device scratch ----------------
__device__ float d_W1r[HH*3];
__device__ float d_A1r[12];
__device__ float d_B1r[HH*4];
__device__ float d_W2r[EE*HH];     // [e][c]
__device__ float d_A2r[4*HH];      // [r][c]
__device__ float d_B2r[EE*4];      // [e][r]
__device__ float d_Wpr[EE*3];      // [e][j]
__device__ float d_Wd2r[HH];
__device__ float2 d_Wd1p[16*8*32]; // B fragments: [chunk][ktile][lane]
__device__ float d_pe[BB*II*EE];
__device__ float d_ped[BB*II*EE];  // pe - neg_embed
__device__ unsigned d_mask[BB*II*NW];
__device__ int d_inter[BB*II*II];

// TF32 round-to-nearest (matches cublas input rounding)
__device__ __forceinline__ float tf32r(float x) {
    float y;
    asm("cvt.rna.tf32.f32 %0, %1;" : "=f"(y) : "f"(x));
    return y;
}

// ---------------- threefry2x32, key=(0,42) ----------------
__device__ __forceinline__ void threefry_0_42(unsigned x0, unsigned x1,
                                              unsigned& o0, unsigned& o1) {
    const unsigned k0 = 0u, k1 = 42u;
    const unsigned k2 = 0x1BD11BDAu ^ k0 ^ k1;
    unsigned v0 = x0 + k0, v1 = x1 + k1;
#define TF_R(r) { v0 += v1; v1 = (v1 << (r)) | (v1 >> (32 - (r))); v1 ^= v0; }
    TF_R(13) TF_R(15) TF_R(26) TF_R(6)   v0 += k1; v1 += k2 + 1u;
    TF_R(17) TF_R(29) TF_R(16) TF_R(24)  v0 += k2; v1 += k0 + 2u;
    TF_R(13) TF_R(15) TF_R(26) TF_R(6)   v0 += k0; v1 += k1 + 3u;
    TF_R(17) TF_R(29) TF_R(16) TF_R(24)  v0 += k1; v1 += k2 + 4u;
    TF_R(13) TF_R(15) TF_R(26) TF_R(6)   v0 += k2; v1 += k0 + 5u;
#undef TF_R
    o0 = v0; o1 = v1;
}

// ---------------- K0: round weights + pos_embed + pack Wd1 fragments ----------------
__global__ void k_setup(const float* __restrict__ W1, const float* __restrict__ A1,
                        const float* __restrict__ B1, const float* __restrict__ W2,
                        const float* __restrict__ A2, const float* __restrict__ B2,
                        const float* __restrict__ Wp, const float* __restrict__ bp,
                        const float* __restrict__ Wd1, const float* __restrict__ Wd2,
                        const float* __restrict__ pos_coords) {
    int t = threadIdx.x;
    for (int i = t; i < HH*3;  i += 1024) d_W1r[i] = tf32r(W1[i]);
    for (int i = t; i < 12;    i += 1024) d_A1r[i] = tf32r(A1[i]);
    for (int i = t; i < HH*4;  i += 1024) d_B1r[i] = tf32r(B1[i]);
    for (int i = t; i < EE*HH; i += 1024) d_W2r[i] = tf32r(W2[i]);
    for (int i = t; i < 4*HH;  i += 1024) d_A2r[i] = tf32r(A2[i]);
    for (int i = t; i < EE*4;  i += 1024) d_B2r[i] = tf32r(B2[i]);
    for (int i = t; i < EE*3;  i += 1024) d_Wpr[i] = tf32r(Wp[i]);
    for (int i = t; i < HH;    i += 1024) d_Wd2r[i] = tf32r(Wd2[i]);
    for (int i = t; i < 16*8*32; i += 1024) {
        int ch = i >> 8, tl = (i >> 5) & 7, ln = i & 31;
        int e0 = ch*8 + (ln & 3);
        int k  = tl*8 + (ln >> 2);
        d_Wd1p[i] = make_float2(tf32r(Wd1[k*EE + e0]), tf32r(Wd1[k*EE + e0 + 4]));
    }
    __syncthreads();
    for (int i = t; i < BB*II*EE; i += 1024) {
        int bi = i >> 7, e = i & 127;
        float p0 = tf32r(pos_coords[bi*3+0]);
        float p1 = tf32r(pos_coords[bi*3+1]);
        float p2 = tf32r(pos_coords[bi*3+2]);
        d_pe[i] = p0*d_Wpr[e*3] + p1*d_Wpr[e*3+1] + p2*d_Wpr[e*3+2] + bp[e];
    }
}

// ---------------- K1: encoder (TF32-emulated LoRA chain) — UNCHANGED ----------------
__global__ __launch_bounds__(128) void k_encoder(const float* __restrict__ points,
                                                 float* __restrict__ out_pf) {
    __shared__ float sW2r[EE*HH];
    __shared__ float sB2r[EE*4];
    __shared__ float sW1r[HH*3];
    __shared__ float sA1r[12];
    __shared__ float sB1r[HH*4];
    __shared__ float sA2r[4*HH];
    int t = threadIdx.x;
    for (int i = t; i < EE*HH; i += 128) sW2r[i] = d_W2r[i];
    for (int i = t; i < EE*4;  i += 128) sB2r[i] = d_B2r[i];
    for (int i = t; i < HH*3;  i += 128) sW1r[i] = d_W1r[i];
    for (int i = t; i < 12;    i += 128) sA1r[i] = d_A1r[i];
    for (int i = t; i < HH*4;  i += 128) sB1r[i] = d_B1r[i];
    for (int i = t; i < 4*HH;  i += 128) sA2r[i] = d_A2r[i];
    __syncthreads();

    int m = blockIdx.x * 128 + t;
    float p0 = tf32r(points[m*3]), p1 = tf32r(points[m*3+1]), p2 = tf32r(points[m*3+2]);

    float ur[4];
    #pragma unroll
    for (int r = 0; r < 4; r++)
        ur[r] = tf32r(p0*sA1r[r*3] + p1*sA1r[r*3+1] + p2*sA1r[r*3+2]);

    float h1r[HH];
    #pragma unroll 4
    for (int c = 0; c < HH; c++) {
        float t1 = p0*sW1r[c*3] + p1*sW1r[c*3+1] + p2*sW1r[c*3+2];
        float l1 = ur[0]*sB1r[c*4] + ur[1]*sB1r[c*4+1] + ur[2]*sB1r[c*4+2] + ur[3]*sB1r[c*4+3];
        float h = t1 + 0.25f*l1;
        h1r[c] = tf32r(fmaxf(h, 0.f));
    }

    float vr[4];
    #pragma unroll
    for (int r = 0; r < 4; r++) {
        float s = 0.f;
        #pragma unroll 8
        for (int c = 0; c < HH; c++) s += h1r[c]*sA2r[r*HH + c];
        vr[r] = tf32r(s);
    }

    float4* pout = (float4*)(out_pf + (size_t)m * EE);
    #pragma unroll 2
    for (int e4 = 0; e4 < 32; e4++) {
        float o[4];
        #pragma unroll
        for (int q = 0; q < 4; q++) {
            int e = e4*4 + q;
            float s = 0.f;
            #pragma unroll 8
            for (int c = 0; c < HH; c++) s += h1r[c]*sW2r[e*HH + c];
            float l2 = vr[0]*sB2r[e*4] + vr[1]*sB2r[e*4+1] + vr[2]*sB2r[e*4+2] + vr[3]*sB2r[e*4+3];
            o[q] = s + 0.25f*l2;
        }
        pout[e4] = make_float4(o[0], o[1], o[2], o[3]);
    }
}

// ---------------- K2/K4: tensor-core TF32 decode — 2-prompt fused passes ----------------
// grid (ntile=64, b=2, pg=2), 256 threads. Each block: 16 prompts in 8 fused
// passes. A-fragments from pf registers + smem pe; B-fragment LDS shared by
// the two prompts of a pass. One barrier per pass via slg double-buffer.
__global__ __launch_bounds__(256) void k_decode_mma(const float* __restrict__ pf,
                                                    const float* __restrict__ pesrc,
                                                    const float* __restrict__ bd1,
                                                    const float* __restrict__ bd2,
                                                    int mode, float* __restrict__ out) {
    extern __shared__ float sm[];
    float* swb  = sm;                 // 4096 float2 (32KB)
    float* spe  = swb + 8192;         // [16][128] pe rows (8KB)
    float* sbd1 = spe + 16*EE;        // 64
    float* sw2  = sbd1 + 64;          // 64
    float* slg  = sw2 + 64;           // 2 x 256 (double buffer)

    int t = threadIdx.x;
    int ntile = blockIdx.x, b = blockIdx.y, pg = blockIdx.z;
    int base = ntile * 128;
    int i0 = pg * 16;
    int lane = t & 31, w = t >> 5;

    {
        float2* swb2 = (float2*)swb;
        #pragma unroll 4
        for (int i = t; i < 4096; i += 256) swb2[i] = d_Wd1p[i];
        const float4* pesrc4 = (const float4*)(pesrc + (size_t)(b*II + i0)*EE);
        float4* spe4 = (float4*)spe;
        #pragma unroll 2
        for (int i = t; i < 16*EE/4; i += 256) spe4[i] = pesrc4[i];
        if (t < 64) { sbd1[t] = bd1[t]; sw2[t] = d_Wd2r[t]; }
    }
    float bd2v = bd2[0];

    // pf A-fragment registers: rows n1, n1+8; cols (lane&3)+8ch, +4
    int n1 = base + w*16 + (lane >> 2);
    const float* pf1 = pf + ((size_t)(b*NN) + n1) * EE;
    const float* pf2 = pf1 + 8*EE;
    int c0b = lane & 3;
    float pa[16], pb[16], pc[16], pd[16];
    #pragma unroll
    for (int ch = 0; ch < 16; ch++) {
        int c0 = c0b + 8*ch;
        pa[ch] = __ldg(pf1 + c0);
        pb[ch] = __ldg(pf2 + c0);
        pc[ch] = __ldg(pf1 + c0 + 4);
        pd[ch] = __ldg(pf2 + c0 + 4);
    }
    __syncthreads();

    #pragma unroll 1
    for (int pass = 0; pass < 8; pass++) {
        const float* peA = spe + (pass*2)*EE;
        const float* peB = peA + EE;
        float* slgbuf = slg + (pass & 1) * 256;

        float accA[8][4], accB[8][4];
        #pragma unroll
        for (int tl = 0; tl < 8; tl++) {
            accA[tl][0]=0.f; accA[tl][1]=0.f; accA[tl][2]=0.f; accA[tl][3]=0.f;
            accB[tl][0]=0.f; accB[tl][1]=0.f; accB[tl][2]=0.f; accB[tl][3]=0.f;
        }
        #pragma unroll
        for (int ch = 0; ch < 16; ch++) {
            float pA0 = peA[c0b + 8*ch], pA1 = peA[c0b + 8*ch + 4];
            float pB0 = peB[c0b + 8*ch], pB1 = peB[c0b + 8*ch + 4];
            unsigned aA0 = __float_as_uint(tf32r(pa[ch] + pA0));
            unsigned aA1 = __float_as_uint(tf32r(pb[ch] + pA0));
            unsigned aA2 = __float_as_uint(tf32r(pc[ch] + pA1));
            unsigned aA3 = __float_as_uint(tf32r(pd[ch] + pA1));
            unsigned aB0 = __float_as_uint(tf32r(pa[ch] + pB0));
            unsigned aB1 = __float_as_uint(tf32r(pb[ch] + pB0));
            unsigned aB2 = __float_as_uint(tf32r(pc[ch] + pB1));
            unsigned aB3 = __float_as_uint(tf32r(pd[ch] + pB1));
            #pragma unroll
            for (int tl = 0; tl < 8; tl++) {
                float2 bb = ((float2*)swb)[(ch*8 + tl)*32 + lane];
                unsigned b0 = __float_as_uint(bb.x), b1 = __float_as_uint(bb.y);
                asm volatile(
                    "mma.sync.aligned.m16n8k8.row.col.f32.tf32.tf32.f32 "
                    "{%0,%1,%2,%3}, {%4,%5,%6,%7}, {%8,%9}, {%0,%1,%2,%3};"
                    : "+f"(accA[tl][0]), "+f"(accA[tl][1]), "+f"(accA[tl][2]), "+f"(accA[tl][3])
                    : "r"(aA0), "r"(aA1), "r"(aA2), "r"(aA3), "r"(b0), "r"(b1));
                asm volatile(
                    "mma.sync.aligned.m16n8k8.row.col.f32.tf32.tf32.f32 "
                    "{%0,%1,%2,%3}, {%4,%5,%6,%7}, {%8,%9}, {%0,%1,%2,%3};"
                    : "+f"(accB[tl][0]), "+f"(accB[tl][1]), "+f"(accB[tl][2]), "+f"(accB[tl][3])
                    : "r"(aB0), "r"(aB1), "r"(aB2), "r"(aB3), "r"(b0), "r"(b1));
            }
        }

        // epilogue — per prompt identical to R15
        float p0A = 0.f, p1A = 0.f, p0B = 0.f, p1B = 0.f;
        #pragma unroll
        for (int tl = 0; tl < 8; tl++) {
            int k0 = tl*8 + 2*(lane & 3);
            float h;
            h = tf32r(fmaxf(accA[tl][0] + sbd1[k0],   0.f)); p0A += h * sw2[k0];
            h = tf32r(fmaxf(accA[tl][1] + sbd1[k0+1], 0.f)); p0A += h * sw2[k0+1];
            h = tf32r(fmaxf(accA[tl][2] + sbd1[k0],   0.f)); p1A += h * sw2[k0];
            h = tf32r(fmaxf(accA[tl][3] + sbd1[k0+1], 0.f)); p1A += h * sw2[k0+1];
            h = tf32r(fmaxf(accB[tl][0] + sbd1[k0],   0.f)); p0B += h * sw2[k0];
            h = tf32r(fmaxf(accB[tl][1] + sbd1[k0+1], 0.f)); p0B += h * sw2[k0+1];
            h = tf32r(fmaxf(accB[tl][2] + sbd1[k0],   0.f)); p1B += h * sw2[k0];
            h = tf32r(fmaxf(accB[tl][3] + sbd1[k0+1], 0.f)); p1B += h * sw2[k0+1];
        }
        p0A += __shfl_xor_sync(0xffffffffu, p0A, 1);
        p0A += __shfl_xor_sync(0xffffffffu, p0A, 2);
        p1A += __shfl_xor_sync(0xffffffffu, p1A, 1);
        p1A += __shfl_xor_sync(0xffffffffu, p1A, 2);
        p0B += __shfl_xor_sync(0xffffffffu, p0B, 1);
        p0B += __shfl_xor_sync(0xffffffffu, p0B, 2);
        p1B += __shfl_xor_sync(0xffffffffu, p1B, 1);
        p1B += __shfl_xor_sync(0xffffffffu, p1B, 2);
        if ((lane & 3) == 0) {
            int r = w*16 + (lane >> 2);
            slgbuf[r]           = bd2v + p0A;
            slgbuf[r + 8]       = bd2v + p1A;
            slgbuf[128 + r]     = bd2v + p0B;
            slgbuf[128 + r + 8] = bd2v + p1B;
        }
        __syncthreads();

        // emit both prompts concurrently: t<128 -> prompt A, t>=128 -> prompt B
        int ip = i0 + pass*2 + (t >> 7);
        int tt = t & 127;
        if (mode == 0) {
            unsigned ball = __ballot_sync(0xffffffffu, slgbuf[t] > 0.f);
            if ((t & 31) == 0)
                d_mask[(b*II + ip)*NW + (base >> 5) + (tt >> 5)] = ball;
        } else {
            out[((size_t)(b*II + ip))*NN + base + tt] = slgbuf[t];
        }
        // no trailing barrier: next pass writes the other slg buffer; reuse of
        // this buffer (pass+2) is fenced by the pass+1 barrier.
    }
}

// ---------------- K3a: pairwise mask intersections ----------------
__global__ __launch_bounds__(256) void k_inter() {
    __shared__ unsigned smi[NW];
    int blk = blockIdx.x;            // b*II + i
    int b = blk >> 5;
    int t = threadIdx.x, lane = t & 31, w = t >> 5;
    const unsigned* mi = d_mask + (size_t)blk * NW;
    if (t < NW) smi[t] = mi[t];
    __syncthreads();
    for (int j = w; j < II; j += 8) {
        const unsigned* mj = d_mask + (size_t)(b*II + j) * NW;
        int cnt = 0;
        #pragma unroll
        for (int q = 0; q < 8; q++) {
            int idx = lane + 32*q;
            cnt += __popc(smi[idx] & mj[idx]);
        }
        #pragma unroll
        for (int off = 16; off >= 1; off >>= 1)
            cnt += __shfl_xor_sync(0xffffffffu, cnt, off);
        if (lane == 0) d_inter[blk*II + j] = cnt;
    }
}

// ---------------- K3b: gumbel-max pick + (pe - neg_embed) ----------------
__global__ __launch_bounds__(1024) void k_pick(const float* __restrict__ pos_coords,
                                               const float* __restrict__ bp) {
    __shared__ float s_negc[II * 3];
    int b = blockIdx.x;
    int t = threadIdx.x;
    int i = t >> 5, j = t & 31;

    int cnt_ij = d_inter[b*II*II + i*II + j];
    int cnt_ii = d_inter[b*II*II + i*II + i];
    int cnt_jj = d_inter[b*II*II + j*II + j];

    bool cand = false;
    if (i != j) {
        float inter = (float)cnt_ij;
        float uni = (float)(cnt_ii + cnt_jj) - inter;
        cand = (inter / (uni + 1e-6f)) >= 0.1f;
    }

    unsigned m = (unsigned)(b * 1024 + i * 32 + j);
    unsigned v0, v1;
    threefry_0_42(0u, m, v0, v1);
    unsigned bits = v0 ^ v1;
    unsigned key = cand ? ((((bits >> 9) << 5) | (unsigned)(31 - j)) + 1u) : 0u;
    #pragma unroll
    for (int off = 16; off >= 1; off >>= 1) {
        unsigned o = __shfl_xor_sync(0xffffffffu, key, off);
        key = key > o ? key : o;
    }
    if (j == 0) {
        float c0 = 0.f, c1 = 0.f, c2 = 0.f;
        if (key) {
            int idx = 31 - (int)((key - 1u) & 31u);
            c0 = pos_coords[(b*II + idx)*3 + 0];
            c1 = pos_coords[(b*II + idx)*3 + 1];
            c2 = pos_coords[(b*II + idx)*3 + 2];
        }
        s_negc[i*3 + 0] = c0; s_negc[i*3 + 1] = c1; s_negc[i*3 + 2] = c2;
    }
    __syncthreads();

    for (int idx = t; idx < II * EE; idx += 1024) {
        int ii = idx >> 7, e = idx & 127;
        float c0 = tf32r(s_negc[ii*3+0]);
        float c1 = tf32r(s_negc[ii*3+1]);
        float c2 = tf32r(s_negc[ii*3+2]);
        float ne = c0*d_Wpr[e*3] + c1*d_Wpr[e*3+1] + c2*d_Wpr[e*3+2] + bp[e];
        d_ped[b*II*EE + idx] = d_pe[b*II*EE + idx] - ne;
    }
}

// ---------------- launch ----------------
extern "C" void kernel_launch(void* const* d_in, const int* in_sizes, int n_in,
                              void* d_out, int out_size) {
    const float* points     = (const float*)d_in[0];
    const float* pos_coords = (const float*)d_in[1];
    const float* W1  = (const float*)d_in[2];
    const float* A1  = (const float*)d_in[3];
    const float* B1  = (const float*)d_in[4];
    const float* W2  = (const float*)d_in[5];
    const float* A2  = (const float*)d_in[6];
    const float* B2  = (const float*)d_in[7];
    const float* Wp  = (const float*)d_in[8];
    const float* bp  = (const float*)d_in[9];
    const float* Wd1 = (const float*)d_in[10];
    const float* bd1 = (const float*)d_in[11];
    const float* Wd2 = (const float*)d_in[12];
    const float* bd2 = (const float*)d_in[13];

    float* out = (float*)d_out;
    float* out_refined = out;                      // [2,32,8192]
    float* out_pf = out + (size_t)BB * II * NN;    // [2,8192,128]

    static float* d_pe_ptr = nullptr;
    static float* d_ped_ptr = nullptr;
    if (!d_pe_ptr)  cudaGetSymbolAddress((void**)&d_pe_ptr,  d_pe);
    if (!d_ped_ptr) cudaGetSymbolAddress((void**)&d_ped_ptr, d_ped);

    int smem_bytes = (8192 + 16*EE + 64 + 64 + 512) * 4;
    cudaFuncSetAttribute(k_decode_mma, cudaFuncAttributeMaxDynamicSharedMemorySize, smem_bytes);

    k_setup<<<1, 1024>>>(W1, A1, B1, W2, A2, B2, Wp, bp, Wd1, Wd2, pos_coords);
    k_encoder<<<128, 128>>>(points, out_pf);
    dim3 dgrid(NN/128, BB, 2);
    k_decode_mma<<<dgrid, 256, smem_bytes>>>(out_pf, d_pe_ptr, bd1, bd2, 0, nullptr);
    k_inter<<<BB*II, 256>>>();
    k_pick<<<BB, 1024>>>(pos_coords, bp);
    k_decode_mma<<<dgrid, 256, smem_bytes>>>(out_pf, d_ped_ptr, bd1, bd2, 1, out_refined);
}